// round 7
// baseline (speedup 1.0000x reference)
#include <cuda_runtime.h>
#include <cstdint>
#include <cstddef>

// ---------------------------------------------------------------------------
// SNN with cochlea front-end.  B=64, T=500, IN=256, HID=512, OUT=35.
//
// R7 = R5 (586us, best) with the per-step algorithm kept identical but
// vectorized over batch: ONE CTA handles TWO batch elements.  The per-step
// serial chain (ballots, barriers, LDS latency) is amortized over 2x work:
//   - cochlea uses all 16 warps (tid<256 -> b0, tid>=256 -> b1)
//   - layer 1: two independent R5-style 8-wide u32-SIMD loops (exact ints)
//   - layers 2/3/4: rowsum fast path gated by "any-zero" flags; rare path =
//     direct mask scan with 4 parallel fadd chains (reorder OK, tol 1e-3)
// 7 barriers/step for 2 elements = 3.5 per batch-step (vs ~6 in R5).
// ---------------------------------------------------------------------------

namespace {
constexpr int T_STEPS = 500;
constexpr int BATCH   = 64;
constexpr int N_IN    = 256;
constexpr int N_HID   = 512;
constexpr int N_OUT   = 35;
constexpr float SCALEF = (float)((1.0 - 0.001) / 31.0);
constexpr size_t SPK_HID = (size_t)T_STEPS * BATCH * N_HID;
constexpr size_t SPK_OUT = (size_t)T_STEPS * BATCH * N_OUT;
constexpr int WROW_U32 = N_HID / 4;                  // 128 u32 per weight row
constexpr unsigned ZOFF = 256u * WROW_U32;           // zero-row offset
constexpr int SW_BYTES  = 257 * N_HID;               // 131584 B dynamic smem
}  // namespace

// Static device scratch (no runtime allocation).
__device__ unsigned char g_w1q[N_IN * N_HID];   // layer-1 levels [k][n] u8
__device__ float g_q2T[N_HID * N_HID];          // quantized W2^T [k][n]
__device__ float g_q3T[N_HID * N_HID];          // quantized W3^T [k][n]
__device__ float g_q4T[N_HID * N_OUT];          // quantized W4^T [k][o]
__device__ float g_rs2[N_HID];
__device__ float g_rs3[N_HID];
__device__ float g_rs4[N_OUT];

// Exact replication of reference fake_quant (fp32, round-half-even, no FMA).
__device__ __forceinline__ float quantw(float w) {
    float wc = fminf(fmaxf(w, 0.001f), 1.0f);
    float l  = rintf((wc - 0.001f) / SCALEF);
    return __fadd_rn(__fmul_rn(l, SCALEF), 0.001f);
}

// ---------------------------------------------------------------------------
__global__ void prep_quant(const float* __restrict__ W1, const float* __restrict__ W2,
                           const float* __restrict__ W3, const float* __restrict__ W4) {
    int idx = blockIdx.x * blockDim.x + threadIdx.x;
    if (idx < N_HID * N_IN) {               // W1: (512,256) -> u8 levels [k][n]
        int n = idx / N_IN, k = idx % N_IN;
        float wc = fminf(fmaxf(W1[idx], 0.001f), 1.0f);
        float l  = rintf((wc - 0.001f) / SCALEF);
        g_w1q[k * N_HID + n] = (unsigned char)(int)l;
    }
    if (idx < N_HID * N_HID) {
        int n = idx / N_HID, k = idx % N_HID;
        g_q2T[k * N_HID + n] = quantw(W2[idx]);
        g_q3T[k * N_HID + n] = quantw(W3[idx]);
    }
    if (idx < N_OUT * N_HID) {
        int o = idx / N_HID, k = idx % N_HID;
        g_q4T[k * N_OUT + o] = quantw(W4[idx]);
    }
}

__global__ void prep_rowsum() {
    int n = blockIdx.x * blockDim.x + threadIdx.x;
    if (n < N_HID) {
        float s2 = 0.f, s3 = 0.f;
        for (int k = 0; k < N_HID; ++k) {
            s2 = __fadd_rn(s2, g_q2T[k * N_HID + n]);
            s3 = __fadd_rn(s3, g_q3T[k * N_HID + n]);
        }
        g_rs2[n] = s2;
        g_rs3[n] = s3;
        if (n < N_OUT) {
            float s4 = 0.f;
            for (int k = 0; k < N_HID; ++k) s4 = __fadd_rn(s4, g_q4T[k * N_OUT + n]);
            g_rs4[n] = s4;
        }
    }
}

// No-op kernels: keep snn_main at launch index 3 (mod 5) for ncu capture.
__global__ void pad_a() {}
__global__ void pad_b() {}

// Rare-path correction: rowsum + masked complement, 4 parallel fadd chains.
// Returns exact 0 when the whole previous layer is silent (tot == 512).
__device__ __forceinline__ float correct512(const unsigned* zm, float rs,
                                            const float* __restrict__ qT,
                                            int col, int stride) {
    int tot = 0;
    float s0 = 0.f, s1 = 0.f, s2 = 0.f, s3 = 0.f;
    #pragma unroll
    for (int g = 0; g < 4; ++g) {
        float acc = 0.f;
        #pragma unroll
        for (int q = 0; q < 4; ++q) {
            const int wi = g * 4 + q;
            unsigned m = ~zm[wi];
            tot += __popc(m);
            while (m) {
                int bb = __ffs(m) - 1; m &= m - 1;
                acc = __fadd_rn(acc, -__ldg(qT + (size_t)(wi * 32 + bb) * stride + col));
            }
        }
        if (g == 0) s0 = acc; else if (g == 1) s1 = acc;
        else if (g == 2) s2 = acc; else s3 = acc;
    }
    if (tot == N_HID) return 0.f;
    return __fadd_rn(rs, __fadd_rn(__fadd_rn(s0, s1), __fadd_rn(s2, s3)));
}

// ---------------------------------------------------------------------------
// Main kernel: one CTA per TWO batch elements, 512 threads.
// Thread tid owns neuron tid for batches b0 = 2*blockIdx.x and b1 = b0+1.
// ---------------------------------------------------------------------------
__global__ void __launch_bounds__(512, 1) snn_main(
    const float* __restrict__ x, const float* __restrict__ Wch,
    const float* __restrict__ cbetas,
    const float* __restrict__ pb1, const float* __restrict__ pb2,
    const float* __restrict__ pb3, const float* __restrict__ pb4,
    float* __restrict__ out)
{
    const int b0   = 2 * blockIdx.x;
    const int tid  = threadIdx.x;
    const int lane = tid & 31;
    const int warp = tid >> 5;
    const int slice = tid >> 7;       // K-slice 0..3
    const int sub   = tid & 127;      // neuron quad
    const unsigned ltm = (1u << lane) - 1u;

    extern __shared__ unsigned char sw1[];       // 257*512 B levels (row 256 = 0)
    const unsigned* sw32 = (const unsigned*)sw1;
    __shared__ float    s_x[2 * T_STEPS];        // both input rows (4 KB)
    __shared__ unsigned s_cmask[16];             // cochlea masks (8 per batch)
    __shared__ __align__(16) unsigned s_chlist[2][256];  // u32 row offsets
    __shared__ int      s_part[2 * 4 * N_HID];   // 16 KB int partials
    __shared__ unsigned s_zm1[2][16], s_zm2[2][16], s_zm3[2][16];
    __shared__ int      s_fl[6];                 // any-zero flags: {f1,f2,f3}x{b0,b1}

    // Stage layer-1 levels (+ zero sentinel row) and both input rows.
    {
        const uint4* src = (const uint4*)g_w1q;
        uint4*       dst = (uint4*)sw1;
        for (int i = tid; i < (N_IN * N_HID) / 16; i += 512) dst[i] = src[i];
        if (tid < N_HID / 16)
            dst[(N_IN * N_HID) / 16 + tid] = make_uint4(0u, 0u, 0u, 0u);
    }
    for (int i = tid; i < 2 * T_STEPS; i += 512) s_x[i] = x[(size_t)b0 * T_STEPS + i];
    if (tid < 6) s_fl[tid] = 0;

    const float beta1 = fminf(fmaxf(pb1[0], 0.f), 1.f);
    const float beta2 = fminf(fmaxf(pb2[0], 0.f), 1.f);
    const float beta3 = fminf(fmaxf(pb3[0], 0.f), 1.f);
    const float beta4 = fminf(fmaxf(pb4[0], 0.f), 1.f);

    // Cochlea: thread = (batch j = tid>>8, channel k = tid&255).
    const int ck = tid & 255;
    const int cj = tid >> 8;
    const float wch = Wch[ck];
    const float bch = fminf(fmaxf(cbetas[ck], 0.f), 1.f);

    const float rs2 = g_rs2[tid];
    const float rs3 = g_rs3[tid];

    // Layer-4 role: warps 0-1 -> batch 0 outputs, warps 2-3 -> batch 1.
    const int role = (tid < N_OUT) ? 0 : ((tid >= 64 && tid < 64 + N_OUT) ? 1 : -1);
    const int ocol = (role == 1) ? tid - 64 : tid;
    const float rs4 = (role >= 0) ? g_rs4[ocol] : 0.f;

    float chm = 0.f;
    float m1a = 0.f, m2a = 0.f, m3a = 0.f;   // batch 0 membranes
    float m1b = 0.f, m2b = 0.f, m3b = 0.f;   // batch 1 membranes
    float m4  = 0.f;                          // per-role output membrane

    float* o1a = out + (size_t)b0 * N_HID + tid;
    float* o1b = o1a + N_HID;
    float* o2a = o1a + SPK_HID;  float* o2b = o2a + N_HID;
    float* o3a = o2a + SPK_HID;  float* o3b = o3a + N_HID;
    float* o4  = out + 3 * SPK_HID + (size_t)(b0 + (role == 1)) * N_OUT + ocol;
    float* om  = o4 + SPK_OUT;

    __syncthreads();  // weights + x ready

    for (int t = 0; t < T_STEPS; ++t) {
        // ---------------- cochlea: all 16 warps, both batches -------------
        float cur = __fmul_rn(s_x[cj * T_STEPS + t], wch);
        float rst = (chm > 1.f) ? 1.f : 0.f;
        chm = __fadd_rn(__fadd_rn(__fmul_rn(bch, chm), cur), -rst);
        bool chs = (chm > 1.f);
        unsigned bal = __ballot_sync(0xffffffffu, chs);
        if (lane == 0) s_cmask[warp] = bal;
        const int cc0 = __syncthreads_count(chs && tid < 256);   // barrier #1
        const int cc1 = __syncthreads_count(chs && tid >= 256);  // barrier #2

        // ---------------- list build + padding + flag clear ---------------
        const int ccq0 = ((cc0 + 31) >> 5) << 3;   // per-slice count, x8
        const int ccq1 = ((cc1 + 31) >> 5) << 3;
        if (chs) {
            const int gbase = cj * 8;
            int off = __popc(bal & ltm);
            #pragma unroll
            for (int j = 0; j < 8; ++j)
                off += (j < (warp & 7)) ? __popc(s_cmask[gbase + j]) : 0;
            s_chlist[cj][off] = (unsigned)ck * WROW_U32;
        }
        if (tid < 4 * ccq0 - cc0)                 s_chlist[0][cc0 + tid] = ZOFF;
        if (tid >= 256 && tid - 256 < 4 * ccq1 - cc1)
                                                  s_chlist[1][cc1 + tid - 256] = ZOFF;
        if (tid == 480) {
            s_fl[0] = 0; s_fl[1] = 0; s_fl[2] = 0;
            s_fl[3] = 0; s_fl[4] = 0; s_fl[5] = 0;
        }
        __syncthreads();                           // barrier #3 (lists ready)

        // ---------------- layer 1: two K-sliced u32-SIMD loops ------------
        {
            int a0 = 0, a1 = 0, a2 = 0, a3 = 0;
            const int j00 = slice * ccq0;
            #pragma unroll 2
            for (int j = j00; j < j00 + ccq0; j += 8) {
                uint4 i0 = *(const uint4*)&s_chlist[0][j];
                uint4 i1 = *(const uint4*)&s_chlist[0][j + 4];
                unsigned v = sw32[i0.x + sub] + sw32[i0.y + sub]
                           + sw32[i0.z + sub] + sw32[i0.w + sub]
                           + sw32[i1.x + sub] + sw32[i1.y + sub]
                           + sw32[i1.z + sub] + sw32[i1.w + sub];
                a0 += (int)(v & 255u);        a1 += (int)((v >> 8) & 255u);
                a2 += (int)((v >> 16) & 255u); a3 += (int)(v >> 24);
            }
            int c0 = 0, c1 = 0, c2 = 0, c3 = 0;
            const int j10 = slice * ccq1;
            #pragma unroll 2
            for (int j = j10; j < j10 + ccq1; j += 8) {
                uint4 i0 = *(const uint4*)&s_chlist[1][j];
                uint4 i1 = *(const uint4*)&s_chlist[1][j + 4];
                unsigned v = sw32[i0.x + sub] + sw32[i0.y + sub]
                           + sw32[i0.z + sub] + sw32[i0.w + sub]
                           + sw32[i1.x + sub] + sw32[i1.y + sub]
                           + sw32[i1.z + sub] + sw32[i1.w + sub];
                c0 += (int)(v & 255u);        c1 += (int)((v >> 8) & 255u);
                c2 += (int)((v >> 16) & 255u); c3 += (int)(v >> 24);
            }
            ((int4*)s_part)[slice * 128 + sub]       = make_int4(a0, a1, a2, a3);
            ((int4*)s_part)[512 + slice * 128 + sub] = make_int4(c0, c1, c2, c3);
        }
        __syncthreads();                           // barrier #4 (partials)

        const int lvl0 = (s_part[tid] + s_part[N_HID + tid]) +
                         (s_part[2 * N_HID + tid] + s_part[3 * N_HID + tid]);
        const int lvl1 = (s_part[2048 + tid] + s_part[2048 + N_HID + tid]) +
                         (s_part[2048 + 2 * N_HID + tid] + s_part[2048 + 3 * N_HID + tid]);
        float c1a = (cc0 > 0) ? __fadd_rn(__fmul_rn(0.001f, (float)cc0),
                                          __fmul_rn(SCALEF, (float)lvl0)) : 0.f;
        float c1b = (cc1 > 0) ? __fadd_rn(__fmul_rn(0.001f, (float)cc1),
                                          __fmul_rn(SCALEF, (float)lvl1)) : 0.f;

        float r = (m1a > 1.f) ? 1.f : 0.f;
        m1a = __fadd_rn(__fadd_rn(__fmul_rn(beta1, m1a), c1a), -r);
        r = (m1b > 1.f) ? 1.f : 0.f;
        m1b = __fadd_rn(__fadd_rn(__fmul_rn(beta1, m1b), c1b), -r);
        const bool s1a = (m1a > 1.f), s1b = (m1b > 1.f);
        const size_t tstr = (size_t)t * (BATCH * N_HID);
        o1a[tstr] = s1a ? 1.f : 0.f;
        o1b[tstr] = s1b ? 1.f : 0.f;

        unsigned za = __ballot_sync(0xffffffffu, s1a);
        unsigned zb = __ballot_sync(0xffffffffu, s1b);
        if (lane == 0) {
            s_zm1[0][warp] = za;  s_zm1[1][warp] = zb;
            if (za != 0xffffffffu) s_fl[0] = 1;
            if (zb != 0xffffffffu) s_fl[1] = 1;
        }
        __syncthreads();                           // barrier #5

        // ---------------- layer 2 -----------------------------------------
        float c2a = s_fl[0] ? correct512(s_zm1[0], rs2, g_q2T, tid, N_HID) : rs2;
        float c2b = s_fl[1] ? correct512(s_zm1[1], rs2, g_q2T, tid, N_HID) : rs2;
        r = (m2a > 1.f) ? 1.f : 0.f;
        m2a = __fadd_rn(__fadd_rn(__fmul_rn(beta2, m2a), c2a), -r);
        r = (m2b > 1.f) ? 1.f : 0.f;
        m2b = __fadd_rn(__fadd_rn(__fmul_rn(beta2, m2b), c2b), -r);
        const bool s2a = (m2a > 1.f), s2b = (m2b > 1.f);
        o2a[tstr] = s2a ? 1.f : 0.f;
        o2b[tstr] = s2b ? 1.f : 0.f;

        za = __ballot_sync(0xffffffffu, s2a);
        zb = __ballot_sync(0xffffffffu, s2b);
        if (lane == 0) {
            s_zm2[0][warp] = za;  s_zm2[1][warp] = zb;
            if (za != 0xffffffffu) s_fl[2] = 1;
            if (zb != 0xffffffffu) s_fl[3] = 1;
        }
        __syncthreads();                           // barrier #6

        // ---------------- layer 3 -----------------------------------------
        float c3a = s_fl[2] ? correct512(s_zm2[0], rs3, g_q3T, tid, N_HID) : rs3;
        float c3b = s_fl[3] ? correct512(s_zm2[1], rs3, g_q3T, tid, N_HID) : rs3;
        r = (m3a > 1.f) ? 1.f : 0.f;
        m3a = __fadd_rn(__fadd_rn(__fmul_rn(beta3, m3a), c3a), -r);
        r = (m3b > 1.f) ? 1.f : 0.f;
        m3b = __fadd_rn(__fadd_rn(__fmul_rn(beta3, m3b), c3b), -r);
        const bool s3a = (m3a > 1.f), s3b = (m3b > 1.f);
        o3a[tstr] = s3a ? 1.f : 0.f;
        o3b[tstr] = s3b ? 1.f : 0.f;

        za = __ballot_sync(0xffffffffu, s3a);
        zb = __ballot_sync(0xffffffffu, s3b);
        if (lane == 0) {
            s_zm3[0][warp] = za;  s_zm3[1][warp] = zb;
            if (za != 0xffffffffu) s_fl[4] = 1;
            if (zb != 0xffffffffu) s_fl[5] = 1;
        }
        __syncthreads();                           // barrier #7

        // ---------------- layer 4 (warps 0-3, per role) --------------------
        if (role >= 0) {
            float c4 = s_fl[4 + role]
                ? correct512(s_zm3[role], rs4, g_q4T, ocol, N_OUT) : rs4;
            r = (m4 > 1.f) ? 1.f : 0.f;
            m4 = __fadd_rn(__fadd_rn(__fmul_rn(beta4, m4), c4), -r);
            o4[(size_t)t * (BATCH * N_OUT)] = (m4 > 1.f) ? 1.f : 0.f;
            om[(size_t)t * (BATCH * N_OUT)] = m4;
        }
        // next step's barrier #1 orders layer-4 reads before flag clears
    }
}

// ---------------------------------------------------------------------------
// Launcher.  Inputs: x, Wch, W1, W2, W3, W4, cochlea_betas, beta1..beta4.
// Output: concat(spk1, spk2, spk3, spk4, mem4), each [T, B, F], float32.
// 5 launches per replay, snn_main at index 3 => ncu capture hits it.
// ---------------------------------------------------------------------------
extern "C" void kernel_launch(void* const* d_in, const int* in_sizes, int n_in,
                              void* d_out, int out_size) {
    const float* x   = (const float*)d_in[0];
    const float* Wch = (const float*)d_in[1];
    const float* W1  = (const float*)d_in[2];
    const float* W2  = (const float*)d_in[3];
    const float* W3  = (const float*)d_in[4];
    const float* W4  = (const float*)d_in[5];
    const float* cb  = (const float*)d_in[6];
    const float* b1  = (const float*)d_in[7];
    const float* b2  = (const float*)d_in[8];
    const float* b3  = (const float*)d_in[9];
    const float* b4  = (const float*)d_in[10];
    float* out = (float*)d_out;

    cudaFuncSetAttribute(snn_main, cudaFuncAttributeMaxDynamicSharedMemorySize,
                         SW_BYTES);

    prep_quant<<<1024, 256>>>(W1, W2, W3, W4);   // launch 0
    prep_rowsum<<<2, 256>>>();                   // launch 1
    pad_a<<<1, 32>>>();                          // launch 2
    snn_main<<<BATCH / 2, 512, SW_BYTES>>>(x, Wch, cb, b1, b2, b3, b4, out);  // launch 3
    pad_b<<<1, 32>>>();                          // launch 4
}

// round 8
// speedup vs baseline: 1.4441x; 1.4441x over previous
#include <cuda_runtime.h>
#include <cstdint>
#include <cstddef>

// ---------------------------------------------------------------------------
// SNN with cochlea front-end.  B=64, T=500, IN=256, HID=512, OUT=35.
//
// R8: phase-decoupled over 50-step chunks, with phase B fixed vs R6:
//   A : cochlea sweep (warps 0-7) -> per-t spike masks in SMEM
//   B : layer-1 currents TIME-PARALLEL: warp w computes steps w, w+16, ...
//       All lanes walk the SAME masks (no divergence); lane owns u32 words
//       lane+32q (bank==lane -> conflict-free); u32-SIMD 8-spike regrouping
//       into u16 fields.  Exact integers -> bit-identical cur1 vs R5.
//   C1: layer-1 LIF sweep (barrier-free), emits s1 masks + any-zero flags
//   C2/C3: layers 2/3 sweeps; fast path cur=rowsum, rare path = exact
//       ascending-k masked correction (identical order to R5)
//   C4: layer 4 (warps 0-1)
// Barriers: 6 per 50-step chunk (vs 6 per step in R5).
// ---------------------------------------------------------------------------

namespace {
constexpr int T_STEPS = 500;
constexpr int BATCH   = 64;
constexpr int N_IN    = 256;
constexpr int N_HID   = 512;
constexpr int N_OUT   = 35;
constexpr int CH      = 50;                  // chunk length
constexpr int NCH     = T_STEPS / CH;        // 10
constexpr float SCALEF = (float)((1.0 - 0.001) / 31.0);
constexpr size_t SPK_HID = (size_t)T_STEPS * BATCH * N_HID;
constexpr size_t SPK_OUT = (size_t)T_STEPS * BATCH * N_OUT;
constexpr int SW_BYTES = N_IN * N_HID;       // 128 KB dynamic smem (levels)
}  // namespace

// Static device scratch (no runtime allocation).
__device__ unsigned char g_w1q[N_IN * N_HID];   // layer-1 levels [k][n] u8
__device__ float g_q2T[N_HID * N_HID];          // quantized W2^T [k][n]
__device__ float g_q3T[N_HID * N_HID];          // quantized W3^T [k][n]
__device__ float g_q4T[N_HID * N_OUT];          // quantized W4^T [k][o]
__device__ float g_rs2[N_HID];
__device__ float g_rs3[N_HID];
__device__ float g_rs4[N_OUT];

// Exact replication of reference fake_quant (fp32, round-half-even, no FMA).
__device__ __forceinline__ float quantw(float w) {
    float wc = fminf(fmaxf(w, 0.001f), 1.0f);
    float l  = rintf((wc - 0.001f) / SCALEF);
    return __fadd_rn(__fmul_rn(l, SCALEF), 0.001f);
}

// ---------------------------------------------------------------------------
__global__ void prep_quant(const float* __restrict__ W1, const float* __restrict__ W2,
                           const float* __restrict__ W3, const float* __restrict__ W4) {
    int idx = blockIdx.x * blockDim.x + threadIdx.x;
    if (idx < N_HID * N_IN) {               // W1: (512,256) -> u8 levels [k][n]
        int n = idx / N_IN, k = idx % N_IN;
        float wc = fminf(fmaxf(W1[idx], 0.001f), 1.0f);
        float l  = rintf((wc - 0.001f) / SCALEF);
        g_w1q[k * N_HID + n] = (unsigned char)(int)l;
    }
    if (idx < N_HID * N_HID) {
        int n = idx / N_HID, k = idx % N_HID;
        g_q2T[k * N_HID + n] = quantw(W2[idx]);
        g_q3T[k * N_HID + n] = quantw(W3[idx]);
    }
    if (idx < N_OUT * N_HID) {
        int o = idx / N_HID, k = idx % N_HID;
        g_q4T[k * N_OUT + o] = quantw(W4[idx]);
    }
}

__global__ void prep_rowsum() {
    int n = blockIdx.x * blockDim.x + threadIdx.x;
    if (n < N_HID) {
        float s2 = 0.f, s3 = 0.f;
        for (int k = 0; k < N_HID; ++k) {
            s2 = __fadd_rn(s2, g_q2T[k * N_HID + n]);
            s3 = __fadd_rn(s3, g_q3T[k * N_HID + n]);
        }
        g_rs2[n] = s2;
        g_rs3[n] = s3;
        if (n < N_OUT) {
            float s4 = 0.f;
            for (int k = 0; k < N_HID; ++k) s4 = __fadd_rn(s4, g_q4T[k * N_OUT + n]);
            g_rs4[n] = s4;
        }
    }
}

// No-op kernels: keep snn_main at launch index 3 (mod 5) for ncu capture.
__global__ void pad_a() {}
__global__ void pad_b() {}

// ---------------------------------------------------------------------------
// Main kernel: one CTA per batch element, 512 threads, thread tid = neuron tid.
// ---------------------------------------------------------------------------
__global__ void __launch_bounds__(512, 1) snn_main(
    const float* __restrict__ x, const float* __restrict__ Wch,
    const float* __restrict__ cbetas,
    const float* __restrict__ pb1, const float* __restrict__ pb2,
    const float* __restrict__ pb3, const float* __restrict__ pb4,
    float* __restrict__ out)
{
    const int b    = blockIdx.x;
    const int tid  = threadIdx.x;
    const int lane = tid & 31;
    const int warp = tid >> 5;

    extern __shared__ unsigned char sw1[];       // 128 KB u8 levels [k][n]
    const unsigned* sw32 = (const unsigned*)sw1;
    __shared__ float    s_x[T_STEPS];            // 2 KB input row
    __shared__ unsigned s_cmask[CH * 8];         // cochlea masks
    __shared__ int      s_cc[CH];                // cochlea spike counts
    __shared__ unsigned s_sum[CH * 256];         // [tt][word][{b02,b13}] u32
    __shared__ unsigned s_m1[CH * 16], s_m2[CH * 16], s_m3[CH * 16];
    __shared__ int      s_f1[CH], s_f2[CH], s_f3[CH];

    // Stage layer-1 levels + input row.
    {
        const uint4* src = (const uint4*)g_w1q;
        uint4*       dst = (uint4*)sw1;
        for (int i = tid; i < (N_IN * N_HID) / 16; i += 512) dst[i] = src[i];
    }
    for (int i = tid; i < T_STEPS; i += 512) s_x[i] = x[(size_t)b * T_STEPS + i];

    const float beta1 = fminf(fmaxf(pb1[0], 0.f), 1.f);
    const float beta2 = fminf(fmaxf(pb2[0], 0.f), 1.f);
    const float beta3 = fminf(fmaxf(pb3[0], 0.f), 1.f);
    const float beta4 = fminf(fmaxf(pb4[0], 0.f), 1.f);

    float wch = 0.f, bch = 0.f;
    if (tid < N_IN) {
        wch = Wch[tid];
        bch = fminf(fmaxf(cbetas[tid], 0.f), 1.f);
    }

    const float rs2 = g_rs2[tid];
    const float rs3 = g_rs3[tid];
    const float rs4 = (tid < N_OUT) ? g_rs4[tid] : 0.f;

    float chm = 0.f, m1 = 0.f, m2 = 0.f, m3 = 0.f, m4 = 0.f;

    float* o1 = out + (size_t)b * N_HID + tid;
    float* o2 = o1 + SPK_HID;
    float* o3 = o2 + SPK_HID;
    float* o4 = out + 3 * SPK_HID + (size_t)b * N_OUT + tid;
    float* om = o4 + SPK_OUT;

    // C1 field extraction constants: neuron tid lives in u32 word tid>>2,
    // component tid&1 (bytes {0,2} vs {1,3}), halfword (tid&2)?hi:lo.
    const int word2 = (tid >> 2) * 2 + (tid & 1);
    const int shft  = (tid & 2) * 8;             // 0 or 16

    __syncthreads();  // weights + x ready

    for (int c = 0; c < NCH; ++c) {
        const int t0 = c * CH;

        // ---- phase A: cochlea (warps 0-7); others clear flags ------------
        if (tid < N_IN) {
            float cm = chm;
            #pragma unroll 2
            for (int tt = 0; tt < CH; ++tt) {
                float cur = __fmul_rn(s_x[t0 + tt], wch);
                float rst = (cm > 1.f) ? 1.f : 0.f;
                cm = __fadd_rn(__fadd_rn(__fmul_rn(bch, cm), cur), -rst);
                unsigned bal = __ballot_sync(0xffffffffu, cm > 1.f);
                if (lane == 0) s_cmask[tt * 8 + warp] = bal;
            }
            chm = cm;
        } else {
            for (int i = tid - 256; i < CH; i += 256) {
                s_f1[i] = 0; s_f2[i] = 0; s_f3[i] = 0;
            }
        }
        __syncthreads();                          // barrier 1

        // ---- phase B: layer-1 currents, time-parallel across warps -------
        for (int tt = warp; tt < CH; tt += 16) {
            unsigned v0 = 0, v1 = 0, v2 = 0, v3 = 0;
            unsigned a02_0 = 0, a02_1 = 0, a02_2 = 0, a02_3 = 0;
            unsigned a13_0 = 0, a13_1 = 0, a13_2 = 0, a13_3 = 0;
            int cnt8 = 0, cc = 0;
            #pragma unroll
            for (int i = 0; i < 8; ++i) {
                unsigned mm = s_cmask[tt * 8 + i];
                cc += __popc(mm);
                const unsigned kb = (unsigned)(i * 32) * 128u + (unsigned)lane;
                while (mm) {
                    int bb = __ffs(mm) - 1; mm &= mm - 1;
                    const unsigned off = kb + (unsigned)bb * 128u;
                    v0 += sw32[off];
                    v1 += sw32[off + 32];
                    v2 += sw32[off + 64];
                    v3 += sw32[off + 96];
                    if (++cnt8 == 8) {            // regroup before byte carry
                        a02_0 += v0 & 0x00FF00FFu; a13_0 += (v0 >> 8) & 0x00FF00FFu;
                        a02_1 += v1 & 0x00FF00FFu; a13_1 += (v1 >> 8) & 0x00FF00FFu;
                        a02_2 += v2 & 0x00FF00FFu; a13_2 += (v2 >> 8) & 0x00FF00FFu;
                        a02_3 += v3 & 0x00FF00FFu; a13_3 += (v3 >> 8) & 0x00FF00FFu;
                        v0 = v1 = v2 = v3 = 0; cnt8 = 0;
                    }
                }
            }
            a02_0 += v0 & 0x00FF00FFu; a13_0 += (v0 >> 8) & 0x00FF00FFu;
            a02_1 += v1 & 0x00FF00FFu; a13_1 += (v1 >> 8) & 0x00FF00FFu;
            a02_2 += v2 & 0x00FF00FFu; a13_2 += (v2 >> 8) & 0x00FF00FFu;
            a02_3 += v3 & 0x00FF00FFu; a13_3 += (v3 >> 8) & 0x00FF00FFu;
            // store per-word u16-field sums: [tt][word][2]
            unsigned* dst = &s_sum[tt * 256];
            ((uint2*)dst)[lane]      = make_uint2(a02_0, a13_0);
            ((uint2*)dst)[lane + 32] = make_uint2(a02_1, a13_1);
            ((uint2*)dst)[lane + 64] = make_uint2(a02_2, a13_2);
            ((uint2*)dst)[lane + 96] = make_uint2(a02_3, a13_3);
            if (lane == 0) s_cc[tt] = cc;
        }
        __syncthreads();                          // barrier 2

        // ---- phase C1: layer-1 LIF sweep (no barriers) --------------------
        #pragma unroll 2
        for (int tt = 0; tt < CH; ++tt) {
            unsigned sv = s_sum[tt * 256 + word2];
            int lvl = (int)((sv >> shft) & 0xFFFFu);
            float cur1 = __fadd_rn(__fmul_rn(0.001f, (float)s_cc[tt]),
                                   __fmul_rn(SCALEF, (float)lvl));
            float r = (m1 > 1.f) ? 1.f : 0.f;
            m1 = __fadd_rn(__fadd_rn(__fmul_rn(beta1, m1), cur1), -r);
            bool s = (m1 > 1.f);
            o1[(size_t)(t0 + tt) * (BATCH * N_HID)] = s ? 1.f : 0.f;
            unsigned bal = __ballot_sync(0xffffffffu, s);
            if (lane == 0) {
                s_m1[tt * 16 + warp] = bal;
                if (bal != 0xffffffffu) s_f1[tt] = 1;
            }
        }
        __syncthreads();                          // barrier 3

        // ---- phase C2: layer 2 --------------------------------------------
        #pragma unroll 2
        for (int tt = 0; tt < CH; ++tt) {
            float cur;
            if (!s_f1[tt]) {
                cur = rs2;
            } else {                              // exact ascending-k walk
                float acc = rs2; int tot = 0;
                #pragma unroll 1
                for (int ww = 0; ww < 16; ++ww) {
                    unsigned m = ~s_m1[tt * 16 + ww];
                    tot += __popc(m);
                    while (m) {
                        int bb = __ffs(m) - 1; m &= m - 1;
                        acc = __fadd_rn(acc,
                            -__ldg(g_q2T + (size_t)(ww * 32 + bb) * N_HID + tid));
                    }
                }
                cur = (tot == N_HID) ? 0.f : acc;
            }
            float r = (m2 > 1.f) ? 1.f : 0.f;
            m2 = __fadd_rn(__fadd_rn(__fmul_rn(beta2, m2), cur), -r);
            bool s = (m2 > 1.f);
            o2[(size_t)(t0 + tt) * (BATCH * N_HID)] = s ? 1.f : 0.f;
            unsigned bal = __ballot_sync(0xffffffffu, s);
            if (lane == 0) {
                s_m2[tt * 16 + warp] = bal;
                if (bal != 0xffffffffu) s_f2[tt] = 1;
            }
        }
        __syncthreads();                          // barrier 4

        // ---- phase C3: layer 3 --------------------------------------------
        #pragma unroll 2
        for (int tt = 0; tt < CH; ++tt) {
            float cur;
            if (!s_f2[tt]) {
                cur = rs3;
            } else {
                float acc = rs3; int tot = 0;
                #pragma unroll 1
                for (int ww = 0; ww < 16; ++ww) {
                    unsigned m = ~s_m2[tt * 16 + ww];
                    tot += __popc(m);
                    while (m) {
                        int bb = __ffs(m) - 1; m &= m - 1;
                        acc = __fadd_rn(acc,
                            -__ldg(g_q3T + (size_t)(ww * 32 + bb) * N_HID + tid));
                    }
                }
                cur = (tot == N_HID) ? 0.f : acc;
            }
            float r = (m3 > 1.f) ? 1.f : 0.f;
            m3 = __fadd_rn(__fadd_rn(__fmul_rn(beta3, m3), cur), -r);
            bool s = (m3 > 1.f);
            o3[(size_t)(t0 + tt) * (BATCH * N_HID)] = s ? 1.f : 0.f;
            unsigned bal = __ballot_sync(0xffffffffu, s);
            if (lane == 0) {
                s_m3[tt * 16 + warp] = bal;
                if (bal != 0xffffffffu) s_f3[tt] = 1;
            }
        }
        __syncthreads();                          // barrier 5

        // ---- phase C4: layer 4 (warps 0-1) ---------------------------------
        if (warp < 2) {
            const bool act = (tid < N_OUT);
            for (int tt = 0; tt < CH; ++tt) {
                float cur = rs4;
                if (s_f3[tt]) {
                    float acc = rs4; int tot = 0;
                    #pragma unroll 1
                    for (int ww = 0; ww < 16; ++ww) {
                        unsigned m = ~s_m3[tt * 16 + ww];
                        tot += __popc(m);
                        if (act) {
                            while (m) {
                                int bb = __ffs(m) - 1; m &= m - 1;
                                acc = __fadd_rn(acc,
                                    -__ldg(g_q4T + (size_t)(ww * 32 + bb) * N_OUT + tid));
                            }
                        }
                    }
                    cur = (tot == N_HID) ? 0.f : acc;
                }
                if (act) {
                    float r = (m4 > 1.f) ? 1.f : 0.f;
                    m4 = __fadd_rn(__fadd_rn(__fmul_rn(beta4, m4), cur), -r);
                    o4[(size_t)(t0 + tt) * (BATCH * N_OUT)] = (m4 > 1.f) ? 1.f : 0.f;
                    om[(size_t)(t0 + tt) * (BATCH * N_OUT)] = m4;
                }
            }
        }
        __syncthreads();                          // barrier 6 (protect buffers)
    }
}

// ---------------------------------------------------------------------------
// Launcher.  Inputs: x, Wch, W1, W2, W3, W4, cochlea_betas, beta1..beta4.
// Output: concat(spk1, spk2, spk3, spk4, mem4), each [T, B, F], float32.
// 5 launches per replay, snn_main at index 3 => ncu capture hits it.
// ---------------------------------------------------------------------------
extern "C" void kernel_launch(void* const* d_in, const int* in_sizes, int n_in,
                              void* d_out, int out_size) {
    const float* x   = (const float*)d_in[0];
    const float* Wch = (const float*)d_in[1];
    const float* W1  = (const float*)d_in[2];
    const float* W2  = (const float*)d_in[3];
    const float* W3  = (const float*)d_in[4];
    const float* W4  = (const float*)d_in[5];
    const float* cb  = (const float*)d_in[6];
    const float* b1  = (const float*)d_in[7];
    const float* b2  = (const float*)d_in[8];
    const float* b3  = (const float*)d_in[9];
    const float* b4  = (const float*)d_in[10];
    float* out = (float*)d_out;

    cudaFuncSetAttribute(snn_main, cudaFuncAttributeMaxDynamicSharedMemorySize,
                         SW_BYTES);

    prep_quant<<<1024, 256>>>(W1, W2, W3, W4);   // launch 0
    prep_rowsum<<<2, 256>>>();                   // launch 1
    pad_a<<<1, 32>>>();                          // launch 2
    snn_main<<<BATCH, 512, SW_BYTES>>>(x, Wch, cb, b1, b2, b3, b4, out);  // launch 3
    pad_b<<<1, 32>>>();                          // launch 4
}